// round 2
// baseline (speedup 1.0000x reference)
#include <cuda_runtime.h>
#include <cuda_bf16.h>
#include <math.h>

#define SEQ   2048
#define DIM   4096
#define NH    32
#define NKV   8
#define HD    128
#define QKV_W (DIM + 2 * NKV * HD)   /* 6144: [q 4096 | k 1024 | v 1024] per row */
#define FQS   68                     /* padded stride for d-major Q/K and P tiles */

// Scratch (static device allocations are the sanctioned mechanism)
__device__ float g_qkv[SEQ * QKV_W];   // ~50 MB
__device__ float g_attn[SEQ * DIM];    // ~33 MB

// ---------------------------------------------------------------------------
// GEMM: C[M,N] = A[M,K] * B[N,K]^T   (both row-major, weights are [out,in])
// 128x128 block tile, BK=8, 256 threads, 8x8 register micro-tile.
// ---------------------------------------------------------------------------
__global__ void __launch_bounds__(256) gemm_nt(
    const float* __restrict__ A, int lda,
    const float* __restrict__ B, int ldb,
    float* __restrict__ C, int ldc, int K)
{
    __shared__ float As[8][132];   // k-major, padded: conflict-free transpose writes
    __shared__ float Bs[8][132];

    const int tid = threadIdx.x;
    const int tx = tid & 15, ty = tid >> 4;
    const int m0 = blockIdx.y * 128, n0 = blockIdx.x * 128;

    const int row  = tid >> 1;        // 0..127
    const int quad = (tid & 1) * 4;   // 0 or 4
    const float* Ap = A + (size_t)(m0 + row) * lda + quad;
    const float* Bp = B + (size_t)(n0 + row) * ldb + quad;

    float acc[8][8] = {};

    for (int k0 = 0; k0 < K; k0 += 8) {
        float4 av = *(const float4*)(Ap + k0);
        float4 bv = *(const float4*)(Bp + k0);
        __syncthreads();   // previous iteration's reads complete
        As[quad + 0][row] = av.x; As[quad + 1][row] = av.y;
        As[quad + 2][row] = av.z; As[quad + 3][row] = av.w;
        Bs[quad + 0][row] = bv.x; Bs[quad + 1][row] = bv.y;
        Bs[quad + 2][row] = bv.z; Bs[quad + 3][row] = bv.w;
        __syncthreads();
#pragma unroll
        for (int kk = 0; kk < 8; kk++) {
            float4 a0 = *(const float4*)&As[kk][ty * 8];
            float4 a1 = *(const float4*)&As[kk][ty * 8 + 4];
            float4 b0 = *(const float4*)&Bs[kk][tx * 8];
            float4 b1 = *(const float4*)&Bs[kk][tx * 8 + 4];
            float a[8] = {a0.x, a0.y, a0.z, a0.w, a1.x, a1.y, a1.z, a1.w};
            float b[8] = {b0.x, b0.y, b0.z, b0.w, b1.x, b1.y, b1.z, b1.w};
#pragma unroll
            for (int i = 0; i < 8; i++)
#pragma unroll
                for (int j = 0; j < 8; j++)
                    acc[i][j] += a[i] * b[j];
        }
    }

#pragma unroll
    for (int i = 0; i < 8; i++) {
        float* Cp = C + (size_t)(m0 + ty * 8 + i) * ldc + n0 + tx * 8;
        *(float4*)Cp       = make_float4(acc[i][0], acc[i][1], acc[i][2], acc[i][3]);
        *(float4*)(Cp + 4) = make_float4(acc[i][4], acc[i][5], acc[i][6], acc[i][7]);
    }
}

// ---------------------------------------------------------------------------
// RoPE in-place on Q (heads 0..31) and K (heads 32..39) inside g_qkv.
// ---------------------------------------------------------------------------
__global__ void rope_kernel(const float* __restrict__ cosb,
                            const float* __restrict__ sinb)
{
    int idx = blockIdx.x * blockDim.x + threadIdx.x;   // SEQ * 40 * 64 total
    int p = idx & 63;
    int h = (idx >> 6) % 40;
    int s = idx / (64 * 40);
    float c  = cosb[s * 64 + p];
    float sn = sinb[s * 64 + p];
    float* base = g_qkv + (size_t)s * QKV_W
                + (h < NH ? h * HD : DIM + (h - NH) * HD) + 2 * p;
    float re = base[0], im = base[1];
    base[0] = re * c - im * sn;
    base[1] = re * sn + im * c;
}

// ---------------------------------------------------------------------------
// Flash attention: one block per (64-query tile, head). Online softmax,
// causal tile pruning. GQA: head h reads kv head h/4.
// ---------------------------------------------------------------------------
__global__ void __launch_bounds__(256) flash_kernel()
{
    extern __shared__ float sm[];
    float* Qs = sm;                  // [128 d][68]  (d-major, cols = 64 queries)
    float* Ks = Qs + HD * FQS;       // [128 d][68]  (d-major, cols = 64 keys)
    float* Vs = Ks + HD * FQS;       // [64 k][128 d]
    float* Ps = Vs + 64 * HD;        // [64 q][68]

    const int qt = blockIdx.x, h = blockIdx.y;
    const int q0 = qt * 64;
    const int kvh = h >> 2;          // N_REP = 4
    const int tid = threadIdx.x, tx = tid & 15, ty = tid >> 4;

    // Load Q tile transposed (d-major): global reads coalesced along d.
    const float* qb = g_qkv + (size_t)q0 * QKV_W + h * HD;
    for (int i = tid; i < 64 * HD; i += 256) {
        int d = i & 127, q = i >> 7;
        Qs[d * FQS + q] = qb[(size_t)q * QKV_W + d];
    }

    float m_i[4], l_i[4], O[4][8];
#pragma unroll
    for (int i = 0; i < 4; i++) {
        m_i[i] = -1e30f; l_i[i] = 0.f;
#pragma unroll
        for (int j = 0; j < 8; j++) O[i][j] = 0.f;
    }
    const float scale = 0.08838834764831845f;   // 1/sqrt(128)

    for (int kt = 0; kt <= qt; kt++) {
        __syncthreads();   // previous PV reads of Ks/Vs/Ps complete
        const float* kb = g_qkv + (size_t)kt * 64 * QKV_W + DIM + kvh * HD;
        const float* vb = kb + NKV * HD;
        for (int i = tid; i < 64 * HD; i += 256) {
            int d = i & 127, k = i >> 7;
            Ks[d * FQS + k] = kb[(size_t)k * QKV_W + d];
        }
        for (int i = tid; i < 64 * 32; i += 256) {
            int c = i & 31, k = i >> 5;
            *(float4*)(Vs + k * HD + c * 4) =
                *(const float4*)(vb + (size_t)k * QKV_W + c * 4);
        }
        __syncthreads();

        // scores: s[4q][4k] = Q . K  over d
        float sc[4][4] = {};
#pragma unroll 8
        for (int d = 0; d < HD; d++) {
            float4 a = *(const float4*)&Qs[d * FQS + ty * 4];
            float4 b = *(const float4*)&Ks[d * FQS + tx * 4];
            float ar[4] = {a.x, a.y, a.z, a.w};
            float br[4] = {b.x, b.y, b.z, b.w};
#pragma unroll
            for (int i = 0; i < 4; i++)
#pragma unroll
                for (int j = 0; j < 4; j++)
                    sc[i][j] += ar[i] * br[j];
        }

        const bool diag = (kt == qt);
#pragma unroll
        for (int i = 0; i < 4; i++) {
            const int qrow = q0 + ty * 4 + i;
#pragma unroll
            for (int j = 0; j < 4; j++) {
                sc[i][j] *= scale;
                if (diag && (kt * 64 + tx * 4 + j > qrow)) sc[i][j] = -1e30f;
            }
            float mx = fmaxf(fmaxf(sc[i][0], sc[i][1]), fmaxf(sc[i][2], sc[i][3]));
#pragma unroll
            for (int off = 8; off; off >>= 1)
                mx = fmaxf(mx, __shfl_xor_sync(0xffffffffu, mx, off));
            float mn = fmaxf(m_i[i], mx);
            float ls = 0.f;
#pragma unroll
            for (int j = 0; j < 4; j++) { sc[i][j] = __expf(sc[i][j] - mn); ls += sc[i][j]; }
#pragma unroll
            for (int off = 8; off; off >>= 1)
                ls += __shfl_xor_sync(0xffffffffu, ls, off);
            float alpha = __expf(m_i[i] - mn);
            l_i[i] = l_i[i] * alpha + ls;
            m_i[i] = mn;
            *(float4*)&Ps[(ty * 4 + i) * FQS + tx * 4] =
                make_float4(sc[i][0], sc[i][1], sc[i][2], sc[i][3]);
#pragma unroll
            for (int j = 0; j < 8; j++) O[i][j] *= alpha;
        }
        __syncthreads();   // Ps/Vs visible to all

        // O[4q][8d] += P[4q][64k] @ V[64k][8d]
#pragma unroll 4
        for (int kk = 0; kk < 64; kk++) {
            float4 v0 = *(const float4*)&Vs[kk * HD + tx * 8];
            float4 v1 = *(const float4*)&Vs[kk * HD + tx * 8 + 4];
#pragma unroll
            for (int i = 0; i < 4; i++) {
                float p = Ps[(ty * 4 + i) * FQS + kk];
                O[i][0] += p * v0.x; O[i][1] += p * v0.y;
                O[i][2] += p * v0.z; O[i][3] += p * v0.w;
                O[i][4] += p * v1.x; O[i][5] += p * v1.y;
                O[i][6] += p * v1.z; O[i][7] += p * v1.w;
            }
        }
    }

#pragma unroll
    for (int i = 0; i < 4; i++) {
        float inv = 1.0f / l_i[i];
        float* op = g_attn + (size_t)(q0 + ty * 4 + i) * DIM + h * HD + tx * 8;
        *(float4*)op = make_float4(O[i][0] * inv, O[i][1] * inv,
                                   O[i][2] * inv, O[i][3] * inv);
        *(float4*)(op + 4) = make_float4(O[i][4] * inv, O[i][5] * inv,
                                         O[i][6] * inv, O[i][7] * inv);
    }
}

// ---------------------------------------------------------------------------
#define FLASH_SMEM ((HD * FQS * 2 + 64 * HD + 64 * FQS) * (int)sizeof(float))

extern "C" void kernel_launch(void* const* d_in, const int* in_sizes, int n_in,
                              void* d_out, int out_size)
{
    const float* x  = (const float*)d_in[0];
    const float* wq = (const float*)d_in[1];
    const float* wk = (const float*)d_in[2];
    const float* wv = (const float*)d_in[3];
    const float* wo = (const float*)d_in[4];
    const float* fc = (const float*)d_in[7];   // freqs_cos
    const float* fs = (const float*)d_in[8];   // freqs_sin
    float* out = (float*)d_out;
    (void)in_sizes; (void)n_in; (void)out_size;

    static float* qkv = nullptr;
    static float* attn = nullptr;
    if (!qkv) {   // first call is the uncaptured correctness run
        cudaGetSymbolAddress((void**)&qkv, g_qkv);
        cudaGetSymbolAddress((void**)&attn, g_attn);
        cudaFuncSetAttribute(flash_kernel,
                             cudaFuncAttributeMaxDynamicSharedMemorySize,
                             FLASH_SMEM);
    }

    // QKV projections into fused [S, 6144] scratch
    gemm_nt<<<dim3(DIM / 128, SEQ / 128), 256>>>(x, DIM, wq, DIM, qkv, QKV_W, DIM);
    gemm_nt<<<dim3((NKV * HD) / 128, SEQ / 128), 256>>>(x, DIM, wk, DIM, qkv + DIM, QKV_W, DIM);
    gemm_nt<<<dim3((NKV * HD) / 128, SEQ / 128), 256>>>(x, DIM, wv, DIM, qkv + DIM + NKV * HD, QKV_W, DIM);

    // RoPE on Q + K in place
    rope_kernel<<<SEQ * 40 * 64 / 256, 256>>>(fc, fs);

    // Causal GQA flash attention -> g_attn [S, 4096]
    flash_kernel<<<dim3(SEQ / 64, NH), 256, FLASH_SMEM>>>();

    // Output projection
    gemm_nt<<<dim3(DIM / 128, SEQ / 128), 256>>>(attn, DIM, wo, DIM, out, DIM, DIM);
}

// round 5
// speedup vs baseline: 1.9076x; 1.9076x over previous
#include <cuda_runtime.h>
#include <cuda_bf16.h>
#include <math.h>
#include <cstdint>

#define SEQ   2048
#define DIM   4096
#define NH    32
#define NKV   8
#define HD    128
#define KVD   (NKV * HD)             /* 1024 */
#define QKV_W (DIM + 2 * KVD)        /* 6144: [q 4096 | k 1024 | v 1024] per row */
#define FQS   68                     /* padded stride for d-major Q/K and P tiles */

// ---------------------------------------------------------------------------
// Scratch (__device__ globals — the sanctioned allocation mechanism)
// ---------------------------------------------------------------------------
__device__ float g_qkv[SEQ * QKV_W];
__device__ float g_attn[SEQ * DIM];
__device__ __nv_bfloat16 g_xh[SEQ * DIM],  g_xl[SEQ * DIM];
__device__ __nv_bfloat16 g_wqh[DIM * DIM], g_wql[DIM * DIM];
__device__ __nv_bfloat16 g_wkh[KVD * DIM], g_wkl[KVD * DIM];
__device__ __nv_bfloat16 g_wvh[KVD * DIM], g_wvl[KVD * DIM];
__device__ __nv_bfloat16 g_woh[DIM * DIM], g_wol[DIM * DIM];
__device__ __nv_bfloat16 g_ah[SEQ * DIM],  g_al[SEQ * DIM];

// ---------------------------------------------------------------------------
// fp32 -> bf16 hi/lo split (vectorized x4)
// ---------------------------------------------------------------------------
__global__ void split_kernel(const float* __restrict__ src,
                             __nv_bfloat16* __restrict__ hi,
                             __nv_bfloat16* __restrict__ lo, int n4)
{
    int i = blockIdx.x * blockDim.x + threadIdx.x;
    if (i >= n4) return;
    float4 v = ((const float4*)src)[i];
    __nv_bfloat16 h0 = __float2bfloat16(v.x), h1 = __float2bfloat16(v.y);
    __nv_bfloat16 h2 = __float2bfloat16(v.z), h3 = __float2bfloat16(v.w);
    __nv_bfloat16 l0 = __float2bfloat16(v.x - __bfloat162float(h0));
    __nv_bfloat16 l1 = __float2bfloat16(v.y - __bfloat162float(h1));
    __nv_bfloat16 l2 = __float2bfloat16(v.z - __bfloat162float(h2));
    __nv_bfloat16 l3 = __float2bfloat16(v.w - __bfloat162float(h3));
    ((__nv_bfloat162*)hi)[2 * i]     = __nv_bfloat162(h0, h1);
    ((__nv_bfloat162*)hi)[2 * i + 1] = __nv_bfloat162(h2, h3);
    ((__nv_bfloat162*)lo)[2 * i]     = __nv_bfloat162(l0, l1);
    ((__nv_bfloat162*)lo)[2 * i + 1] = __nv_bfloat162(l2, l3);
}

// ---------------------------------------------------------------------------
// Tensor-core GEMM via mma.sync (HMMA): C[M,N] = A[M,K] * B[N,K]^T, bf16x3
// split with fp32 accumulation. 128x128 tile, BK=32, cp.async double buffer.
// ---------------------------------------------------------------------------
#define GS      72                     /* smem row stride in bf16 (144 B)   */
#define TILE_B  (128 * 144)            /* 18432 B per operand tile          */
#define STAGE_B (4 * TILE_B)           /* Ah | Al | Bh | Bl                 */
#define GEMM_SMEM (2 * STAGE_B)        /* 147456 B                          */

__device__ __forceinline__ uint32_t smem_u32(const void* p) {
    uint32_t a;
    asm("{ .reg .u64 t; cvta.to.shared.u64 t, %1; cvt.u32.u64 %0, t; }"
        : "=r"(a) : "l"(p));
    return a;
}
__device__ __forceinline__ void cp_async16(uint32_t dst, const void* src) {
    asm volatile("cp.async.cg.shared.global [%0], [%1], 16;"
                 :: "r"(dst), "l"(src));
}
__device__ __forceinline__ void mma_bf16(float& d0, float& d1, float& d2, float& d3,
                                         uint32_t a0, uint32_t a1, uint32_t a2, uint32_t a3,
                                         uint32_t b0, uint32_t b1)
{
    asm volatile(
        "mma.sync.aligned.m16n8k16.row.col.f32.bf16.bf16.f32 "
        "{%0,%1,%2,%3}, {%4,%5,%6,%7}, {%8,%9}, {%0,%1,%2,%3};"
        : "+f"(d0), "+f"(d1), "+f"(d2), "+f"(d3)
        : "r"(a0), "r"(a1), "r"(a2), "r"(a3), "r"(b0), "r"(b1));
}

__global__ void __launch_bounds__(256, 1) gemm_mma(
    const __nv_bfloat16* __restrict__ Ah, const __nv_bfloat16* __restrict__ Al,
    const __nv_bfloat16* __restrict__ Bh, const __nv_bfloat16* __restrict__ Bl,
    float* __restrict__ C, int ldc, int K)
{
    extern __shared__ char smc[];
    const uint32_t sbase = smem_u32(smc);
    const int tid = threadIdx.x;
    const int wid = tid >> 5, lane = tid & 31;
    const int warp_m = wid & 1, warp_n = wid >> 1;
    const int g = lane >> 2, t = lane & 3;
    const int m0 = blockIdx.y * 128, n0 = blockIdx.x * 128;

    const __nv_bfloat16* gsrc[4] = {
        Ah + (size_t)m0 * K, Al + (size_t)m0 * K,
        Bh + (size_t)n0 * K, Bl + (size_t)n0 * K };

    float d[4][4][4];
#pragma unroll
    for (int i = 0; i < 4; i++)
#pragma unroll
        for (int j = 0; j < 4; j++)
#pragma unroll
            for (int e = 0; e < 4; e++) d[i][j][e] = 0.f;

    const int nk = K / 32;

    // ---- async stage loader: 4 tiles of [128 rows x 32 bf16] -------------
    auto issue = [&](int s, int buf) {
        const int koff = s * 32;
#pragma unroll
        for (int tile = 0; tile < 4; tile++) {
            const __nv_bfloat16* src = gsrc[tile];
            uint32_t tb = sbase + (uint32_t)buf * STAGE_B + tile * TILE_B;
#pragma unroll
            for (int p = 0; p < 2; p++) {
                int idx = tid + p * 256;          // 0..511
                int r = idx >> 2, c = idx & 3;    // row 0..127, 16B chunk 0..3
                cp_async16(tb + r * 144 + c * 16,
                           src + (size_t)r * K + koff + c * 8);
            }
        }
        asm volatile("cp.async.commit_group;" ::: "memory");
    };

    issue(0, 0);

    for (int s = 0; s < nk; s++) {
        const int buf = s & 1;
        if (s + 1 < nk) {
            issue(s + 1, buf ^ 1);
            asm volatile("cp.async.wait_group 1;" ::: "memory");
        } else {
            asm volatile("cp.async.wait_group 0;" ::: "memory");
        }
        __syncthreads();

        const __nv_bfloat16* As_h = (const __nv_bfloat16*)(smc + buf * STAGE_B);
        const __nv_bfloat16* As_l = (const __nv_bfloat16*)(smc + buf * STAGE_B + TILE_B);
        const __nv_bfloat16* Bs_h = (const __nv_bfloat16*)(smc + buf * STAGE_B + 2 * TILE_B);
        const __nv_bfloat16* Bs_l = (const __nv_bfloat16*)(smc + buf * STAGE_B + 3 * TILE_B);

#pragma unroll
        for (int ks = 0; ks < 2; ks++) {
            const int k0 = ks * 16;
            uint32_t aH[4][4], aL[4][4], bH[4][2], bL[4][2];
#pragma unroll
            for (int mt = 0; mt < 4; mt++) {
                const __nv_bfloat16* pa = As_h + (warp_m * 64 + mt * 16 + g) * GS + k0 + 2 * t;
                aH[mt][0] = *(const uint32_t*)pa;
                aH[mt][1] = *(const uint32_t*)(pa + 8 * GS);
                aH[mt][2] = *(const uint32_t*)(pa + 8);
                aH[mt][3] = *(const uint32_t*)(pa + 8 * GS + 8);
                const __nv_bfloat16* pl = As_l + (warp_m * 64 + mt * 16 + g) * GS + k0 + 2 * t;
                aL[mt][0] = *(const uint32_t*)pl;
                aL[mt][1] = *(const uint32_t*)(pl + 8 * GS);
                aL[mt][2] = *(const uint32_t*)(pl + 8);
                aL[mt][3] = *(const uint32_t*)(pl + 8 * GS + 8);
            }
#pragma unroll
            for (int nt = 0; nt < 4; nt++) {
                const __nv_bfloat16* pb = Bs_h + (warp_n * 32 + nt * 8 + g) * GS + k0 + 2 * t;
                bH[nt][0] = *(const uint32_t*)pb;
                bH[nt][1] = *(const uint32_t*)(pb + 8);
                const __nv_bfloat16* pbl = Bs_l + (warp_n * 32 + nt * 8 + g) * GS + k0 + 2 * t;
                bL[nt][0] = *(const uint32_t*)pbl;
                bL[nt][1] = *(const uint32_t*)(pbl + 8);
            }
#pragma unroll
            for (int mt = 0; mt < 4; mt++)
#pragma unroll
                for (int nt = 0; nt < 4; nt++) {
                    float* dd = d[mt][nt];
                    mma_bf16(dd[0], dd[1], dd[2], dd[3],
                             aH[mt][0], aH[mt][1], aH[mt][2], aH[mt][3],
                             bH[nt][0], bH[nt][1]);
                    mma_bf16(dd[0], dd[1], dd[2], dd[3],
                             aH[mt][0], aH[mt][1], aH[mt][2], aH[mt][3],
                             bL[nt][0], bL[nt][1]);
                    mma_bf16(dd[0], dd[1], dd[2], dd[3],
                             aL[mt][0], aL[mt][1], aL[mt][2], aL[mt][3],
                             bH[nt][0], bH[nt][1]);
                }
        }
        __syncthreads();
    }

    // ---- epilogue --------------------------------------------------------
#pragma unroll
    for (int mt = 0; mt < 4; mt++) {
        const int row = m0 + warp_m * 64 + mt * 16 + g;
#pragma unroll
        for (int nt = 0; nt < 4; nt++) {
            const int col = n0 + warp_n * 32 + nt * 8 + 2 * t;
            *(float2*)(C + (size_t)row * ldc + col) =
                make_float2(d[mt][nt][0], d[mt][nt][1]);
            *(float2*)(C + (size_t)(row + 8) * ldc + col) =
                make_float2(d[mt][nt][2], d[mt][nt][3]);
        }
    }
}

// ---------------------------------------------------------------------------
// RoPE in-place on Q (heads 0..31) and K (heads 32..39) inside g_qkv.
// ---------------------------------------------------------------------------
__global__ void rope_kernel(const float* __restrict__ cosb,
                            const float* __restrict__ sinb)
{
    int idx = blockIdx.x * blockDim.x + threadIdx.x;
    int p = idx & 63;
    int h = (idx >> 6) % 40;
    int s = idx / (64 * 40);
    float c  = cosb[s * 64 + p];
    float sn = sinb[s * 64 + p];
    float* base = g_qkv + (size_t)s * QKV_W
                + (h < NH ? h * HD : DIM + (h - NH) * HD) + 2 * p;
    float re = base[0], im = base[1];
    base[0] = re * c - im * sn;
    base[1] = re * sn + im * c;
}

// ---------------------------------------------------------------------------
// Flash attention (fp32): one block per (64-query tile, head). Online softmax,
// causal tile pruning. GQA: head h reads kv head h/4.
// ---------------------------------------------------------------------------
__global__ void __launch_bounds__(256) flash_kernel()
{
    extern __shared__ float sm[];
    float* Qs = sm;                  // [128 d][68]
    float* Ks = Qs + HD * FQS;       // [128 d][68]
    float* Vs = Ks + HD * FQS;       // [64 k][128 d]
    float* Ps = Vs + 64 * HD;        // [64 q][68]

    const int qt = blockIdx.x, h = blockIdx.y;
    const int q0 = qt * 64;
    const int kvh = h >> 2;
    const int tid = threadIdx.x, tx = tid & 15, ty = tid >> 4;

    const float* qb = g_qkv + (size_t)q0 * QKV_W + h * HD;
    for (int i = tid; i < 64 * HD; i += 256) {
        int d = i & 127, q = i >> 7;
        Qs[d * FQS + q] = qb[(size_t)q * QKV_W + d];
    }

    float m_i[4], l_i[4], O[4][8];
#pragma unroll
    for (int i = 0; i < 4; i++) {
        m_i[i] = -1e30f; l_i[i] = 0.f;
#pragma unroll
        for (int j = 0; j < 8; j++) O[i][j] = 0.f;
    }
    const float scale = 0.08838834764831845f;

    for (int kt = 0; kt <= qt; kt++) {
        __syncthreads();
        const float* kb = g_qkv + (size_t)kt * 64 * QKV_W + DIM + kvh * HD;
        const float* vb = kb + KVD;
        for (int i = tid; i < 64 * HD; i += 256) {
            int d = i & 127, k = i >> 7;
            Ks[d * FQS + k] = kb[(size_t)k * QKV_W + d];
        }
        for (int i = tid; i < 64 * 32; i += 256) {
            int c = i & 31, k = i >> 5;
            *(float4*)(Vs + k * HD + c * 4) =
                *(const float4*)(vb + (size_t)k * QKV_W + c * 4);
        }
        __syncthreads();

        float sc[4][4] = {};
#pragma unroll 8
        for (int dd = 0; dd < HD; dd++) {
            float4 a = *(const float4*)&Qs[dd * FQS + ty * 4];
            float4 b = *(const float4*)&Ks[dd * FQS + tx * 4];
            float ar[4] = {a.x, a.y, a.z, a.w};
            float br[4] = {b.x, b.y, b.z, b.w};
#pragma unroll
            for (int i = 0; i < 4; i++)
#pragma unroll
                for (int j = 0; j < 4; j++)
                    sc[i][j] += ar[i] * br[j];
        }

        const bool diag = (kt == qt);
#pragma unroll
        for (int i = 0; i < 4; i++) {
            const int qrow = q0 + ty * 4 + i;
#pragma unroll
            for (int j = 0; j < 4; j++) {
                sc[i][j] *= scale;
                if (diag && (kt * 64 + tx * 4 + j > qrow)) sc[i][j] = -1e30f;
            }
            float mx = fmaxf(fmaxf(sc[i][0], sc[i][1]), fmaxf(sc[i][2], sc[i][3]));
#pragma unroll
            for (int off = 8; off; off >>= 1)
                mx = fmaxf(mx, __shfl_xor_sync(0xffffffffu, mx, off));
            float mn = fmaxf(m_i[i], mx);
            float ls = 0.f;
#pragma unroll
            for (int j = 0; j < 4; j++) { sc[i][j] = __expf(sc[i][j] - mn); ls += sc[i][j]; }
#pragma unroll
            for (int off = 8; off; off >>= 1)
                ls += __shfl_xor_sync(0xffffffffu, ls, off);
            float alpha = __expf(m_i[i] - mn);
            l_i[i] = l_i[i] * alpha + ls;
            m_i[i] = mn;
            *(float4*)&Ps[(ty * 4 + i) * FQS + tx * 4] =
                make_float4(sc[i][0], sc[i][1], sc[i][2], sc[i][3]);
#pragma unroll
            for (int j = 0; j < 8; j++) O[i][j] *= alpha;
        }
        __syncthreads();

#pragma unroll 4
        for (int kk = 0; kk < 64; kk++) {
            float4 v0 = *(const float4*)&Vs[kk * HD + tx * 8];
            float4 v1 = *(const float4*)&Vs[kk * HD + tx * 8 + 4];
#pragma unroll
            for (int i = 0; i < 4; i++) {
                float p = Ps[(ty * 4 + i) * FQS + kk];
                O[i][0] += p * v0.x; O[i][1] += p * v0.y;
                O[i][2] += p * v0.z; O[i][3] += p * v0.w;
                O[i][4] += p * v1.x; O[i][5] += p * v1.y;
                O[i][6] += p * v1.z; O[i][7] += p * v1.w;
            }
        }
    }

#pragma unroll
    for (int i = 0; i < 4; i++) {
        float inv = 1.0f / l_i[i];
        float* op = g_attn + (size_t)(q0 + ty * 4 + i) * DIM + h * HD + tx * 8;
        *(float4*)op = make_float4(O[i][0] * inv, O[i][1] * inv,
                                   O[i][2] * inv, O[i][3] * inv);
        *(float4*)(op + 4) = make_float4(O[i][4] * inv, O[i][5] * inv,
                                         O[i][6] * inv, O[i][7] * inv);
    }
}

// ---------------------------------------------------------------------------
#define FLASH_SMEM ((HD * FQS * 2 + 64 * HD + 64 * FQS) * (int)sizeof(float))

extern "C" void kernel_launch(void* const* d_in, const int* in_sizes, int n_in,
                              void* d_out, int out_size)
{
    const float* x  = (const float*)d_in[0];
    const float* wq = (const float*)d_in[1];
    const float* wk = (const float*)d_in[2];
    const float* wv = (const float*)d_in[3];
    const float* wo = (const float*)d_in[4];
    const float* fc = (const float*)d_in[7];
    const float* fs = (const float*)d_in[8];
    float* out = (float*)d_out;
    (void)in_sizes; (void)n_in; (void)out_size;

    static float *qkv = nullptr, *attn = nullptr;
    static __nv_bfloat16 *xh, *xl, *wqh, *wql, *wkh, *wkl, *wvh, *wvl, *woh, *wol, *ah, *al;
    if (!qkv) {   // first call is the uncaptured correctness run
        cudaGetSymbolAddress((void**)&qkv, g_qkv);
        cudaGetSymbolAddress((void**)&attn, g_attn);
        cudaGetSymbolAddress((void**)&xh, g_xh);   cudaGetSymbolAddress((void**)&xl, g_xl);
        cudaGetSymbolAddress((void**)&wqh, g_wqh); cudaGetSymbolAddress((void**)&wql, g_wql);
        cudaGetSymbolAddress((void**)&wkh, g_wkh); cudaGetSymbolAddress((void**)&wkl, g_wkl);
        cudaGetSymbolAddress((void**)&wvh, g_wvh); cudaGetSymbolAddress((void**)&wvl, g_wvl);
        cudaGetSymbolAddress((void**)&woh, g_woh); cudaGetSymbolAddress((void**)&wol, g_wol);
        cudaGetSymbolAddress((void**)&ah, g_ah);   cudaGetSymbolAddress((void**)&al, g_al);
        cudaFuncSetAttribute(flash_kernel,
                             cudaFuncAttributeMaxDynamicSharedMemorySize, FLASH_SMEM);
        cudaFuncSetAttribute(gemm_mma,
                             cudaFuncAttributeMaxDynamicSharedMemorySize, GEMM_SMEM);
    }

    // fp32 -> bf16 hi/lo splits
    split_kernel<<<(SEQ * DIM / 4 + 255) / 256, 256>>>(x, xh, xl, SEQ * DIM / 4);
    split_kernel<<<(DIM * DIM / 4 + 255) / 256, 256>>>(wq, wqh, wql, DIM * DIM / 4);
    split_kernel<<<(KVD * DIM / 4 + 255) / 256, 256>>>(wk, wkh, wkl, KVD * DIM / 4);
    split_kernel<<<(KVD * DIM / 4 + 255) / 256, 256>>>(wv, wvh, wvl, KVD * DIM / 4);
    split_kernel<<<(DIM * DIM / 4 + 255) / 256, 256>>>(wo, woh, wol, DIM * DIM / 4);

    // QKV projections (HMMA, bf16x3) into fused [S, 6144] scratch
    gemm_mma<<<dim3(DIM / 128, SEQ / 128), 256, GEMM_SMEM>>>(xh, xl, wqh, wql, qkv, QKV_W, DIM);
    gemm_mma<<<dim3(KVD / 128, SEQ / 128), 256, GEMM_SMEM>>>(xh, xl, wkh, wkl, qkv + DIM, QKV_W, DIM);
    gemm_mma<<<dim3(KVD / 128, SEQ / 128), 256, GEMM_SMEM>>>(xh, xl, wvh, wvl, qkv + DIM + KVD, QKV_W, DIM);

    // RoPE on Q + K in place
    rope_kernel<<<SEQ * 40 * 64 / 256, 256>>>(fc, fs);

    // Causal GQA flash attention -> g_attn [S, 4096]
    flash_kernel<<<dim3(SEQ / 64, NH), 256, FLASH_SMEM>>>();

    // Output projection (HMMA)
    split_kernel<<<(SEQ * DIM / 4 + 255) / 256, 256>>>(attn, ah, al, SEQ * DIM / 4);
    gemm_mma<<<dim3(DIM / 128, SEQ / 128), 256, GEMM_SMEM>>>(ah, al, woh, wol, out, DIM, DIM);
}

// round 6
// speedup vs baseline: 2.8907x; 1.5154x over previous
#include <cuda_runtime.h>
#include <cuda_bf16.h>
#include <math.h>
#include <cstdint>

#define SEQ   2048
#define DIM   4096
#define NH    32
#define NKV   8
#define HD    128
#define KVD   (NKV * HD)             /* 1024 */
#define QKV_W (DIM + 2 * KVD)        /* 6144: [q 4096 | k 1024 | v 1024] per row */

// ---------------------------------------------------------------------------
// Scratch (__device__ globals — the sanctioned allocation mechanism)
// ---------------------------------------------------------------------------
__device__ float g_qkv[SEQ * QKV_W];
__device__ float g_attn[SEQ * DIM];
__device__ __nv_bfloat16 g_xh[SEQ * DIM],  g_xl[SEQ * DIM];
__device__ __nv_bfloat16 g_wqh[DIM * DIM], g_wql[DIM * DIM];
__device__ __nv_bfloat16 g_wkh[KVD * DIM], g_wkl[KVD * DIM];
__device__ __nv_bfloat16 g_wvh[KVD * DIM], g_wvl[KVD * DIM];
__device__ __nv_bfloat16 g_woh[DIM * DIM], g_wol[DIM * DIM];
__device__ __nv_bfloat16 g_ah[SEQ * DIM],  g_al[SEQ * DIM];

// ---------------------------------------------------------------------------
// helpers
// ---------------------------------------------------------------------------
__device__ __forceinline__ uint32_t smem_u32(const void* p) {
    uint32_t a;
    asm("{ .reg .u64 t; cvta.to.shared.u64 t, %1; cvt.u32.u64 %0, t; }"
        : "=r"(a) : "l"(p));
    return a;
}
__device__ __forceinline__ void cp_async16(uint32_t dst, const void* src) {
    asm volatile("cp.async.cg.shared.global [%0], [%1], 16;"
                 :: "r"(dst), "l"(src));
}
__device__ __forceinline__ void mma_bf16(float& d0, float& d1, float& d2, float& d3,
                                         uint32_t a0, uint32_t a1, uint32_t a2, uint32_t a3,
                                         uint32_t b0, uint32_t b1)
{
    asm volatile(
        "mma.sync.aligned.m16n8k16.row.col.f32.bf16.bf16.f32 "
        "{%0,%1,%2,%3}, {%4,%5,%6,%7}, {%8,%9}, {%0,%1,%2,%3};"
        : "+f"(d0), "+f"(d1), "+f"(d2), "+f"(d3)
        : "r"(a0), "r"(a1), "r"(a2), "r"(a3), "r"(b0), "r"(b1));
}
__device__ __forceinline__ void ldsm4(uint32_t& r0, uint32_t& r1, uint32_t& r2,
                                      uint32_t& r3, uint32_t a)
{
    asm volatile("ldmatrix.sync.aligned.m8n8.x4.shared.b16 {%0,%1,%2,%3}, [%4];"
                 : "=r"(r0), "=r"(r1), "=r"(r2), "=r"(r3) : "r"(a));
}
__device__ __forceinline__ void ldsm4t(uint32_t& r0, uint32_t& r1, uint32_t& r2,
                                       uint32_t& r3, uint32_t a)
{
    asm volatile("ldmatrix.sync.aligned.m8n8.x4.trans.shared.b16 {%0,%1,%2,%3}, [%4];"
                 : "=r"(r0), "=r"(r1), "=r"(r2), "=r"(r3) : "r"(a));
}
__device__ __forceinline__ void split4(float4 v, uint2& h, uint2& l) {
    __nv_bfloat16 h0 = __float2bfloat16(v.x), h1 = __float2bfloat16(v.y);
    __nv_bfloat16 h2 = __float2bfloat16(v.z), h3 = __float2bfloat16(v.w);
    __nv_bfloat162 ha(h0, h1), hb(h2, h3);
    __nv_bfloat162 la(__float2bfloat16(v.x - __bfloat162float(h0)),
                      __float2bfloat16(v.y - __bfloat162float(h1)));
    __nv_bfloat162 lb(__float2bfloat16(v.z - __bfloat162float(h2)),
                      __float2bfloat16(v.w - __bfloat162float(h3)));
    h = make_uint2(*(uint32_t*)&ha, *(uint32_t*)&hb);
    l = make_uint2(*(uint32_t*)&la, *(uint32_t*)&lb);
}
__device__ __forceinline__ void split2(float x, float y, uint32_t& h, uint32_t& l) {
    __nv_bfloat16 hx = __float2bfloat16(x), hy = __float2bfloat16(y);
    __nv_bfloat162 hv(hx, hy);
    __nv_bfloat162 lv(__float2bfloat16(x - __bfloat162float(hx)),
                      __float2bfloat16(y - __bfloat162float(hy)));
    h = *(uint32_t*)&hv;
    l = *(uint32_t*)&lv;
}

// ---------------------------------------------------------------------------
// fp32 -> bf16 hi/lo split (vectorized x4)
// ---------------------------------------------------------------------------
__global__ void split_kernel(const float* __restrict__ src,
                             __nv_bfloat16* __restrict__ hi,
                             __nv_bfloat16* __restrict__ lo, int n4)
{
    int i = blockIdx.x * blockDim.x + threadIdx.x;
    if (i >= n4) return;
    float4 v = ((const float4*)src)[i];
    uint2 h, l;
    split4(v, h, l);
    ((uint2*)hi)[i] = h;
    ((uint2*)lo)[i] = l;
}

// ---------------------------------------------------------------------------
// Tensor-core GEMM via mma.sync: C = A * B^T, bf16x3, cp.async double buffer
// (unchanged from the passing R5 kernel)
// ---------------------------------------------------------------------------
#define GS      72
#define TILE_B  (128 * 144)
#define STAGE_B (4 * TILE_B)
#define GEMM_SMEM (2 * STAGE_B)

__global__ void __launch_bounds__(256, 1) gemm_mma(
    const __nv_bfloat16* __restrict__ Ah, const __nv_bfloat16* __restrict__ Al,
    const __nv_bfloat16* __restrict__ Bh, const __nv_bfloat16* __restrict__ Bl,
    float* __restrict__ C, int ldc, int K)
{
    extern __shared__ char smc[];
    const uint32_t sbase = smem_u32(smc);
    const int tid = threadIdx.x;
    const int wid = tid >> 5, lane = tid & 31;
    const int warp_m = wid & 1, warp_n = wid >> 1;
    const int g = lane >> 2, t = lane & 3;
    const int m0 = blockIdx.y * 128, n0 = blockIdx.x * 128;

    const __nv_bfloat16* gsrc[4] = {
        Ah + (size_t)m0 * K, Al + (size_t)m0 * K,
        Bh + (size_t)n0 * K, Bl + (size_t)n0 * K };

    float d[4][4][4];
#pragma unroll
    for (int i = 0; i < 4; i++)
#pragma unroll
        for (int j = 0; j < 4; j++)
#pragma unroll
            for (int e = 0; e < 4; e++) d[i][j][e] = 0.f;

    const int nk = K / 32;

    auto issue = [&](int s, int buf) {
        const int koff = s * 32;
#pragma unroll
        for (int tile = 0; tile < 4; tile++) {
            const __nv_bfloat16* src = gsrc[tile];
            uint32_t tb = sbase + (uint32_t)buf * STAGE_B + tile * TILE_B;
#pragma unroll
            for (int p = 0; p < 2; p++) {
                int idx = tid + p * 256;
                int r = idx >> 2, c = idx & 3;
                cp_async16(tb + r * 144 + c * 16,
                           src + (size_t)r * K + koff + c * 8);
            }
        }
        asm volatile("cp.async.commit_group;" ::: "memory");
    };

    issue(0, 0);

    for (int s = 0; s < nk; s++) {
        const int buf = s & 1;
        if (s + 1 < nk) {
            issue(s + 1, buf ^ 1);
            asm volatile("cp.async.wait_group 1;" ::: "memory");
        } else {
            asm volatile("cp.async.wait_group 0;" ::: "memory");
        }
        __syncthreads();

        const __nv_bfloat16* As_h = (const __nv_bfloat16*)(smc + buf * STAGE_B);
        const __nv_bfloat16* As_l = (const __nv_bfloat16*)(smc + buf * STAGE_B + TILE_B);
        const __nv_bfloat16* Bs_h = (const __nv_bfloat16*)(smc + buf * STAGE_B + 2 * TILE_B);
        const __nv_bfloat16* Bs_l = (const __nv_bfloat16*)(smc + buf * STAGE_B + 3 * TILE_B);

#pragma unroll
        for (int ks = 0; ks < 2; ks++) {
            const int k0 = ks * 16;
            uint32_t aH[4][4], aL[4][4], bH[4][2], bL[4][2];
#pragma unroll
            for (int mt = 0; mt < 4; mt++) {
                const __nv_bfloat16* pa = As_h + (warp_m * 64 + mt * 16 + g) * GS + k0 + 2 * t;
                aH[mt][0] = *(const uint32_t*)pa;
                aH[mt][1] = *(const uint32_t*)(pa + 8 * GS);
                aH[mt][2] = *(const uint32_t*)(pa + 8);
                aH[mt][3] = *(const uint32_t*)(pa + 8 * GS + 8);
                const __nv_bfloat16* pl = As_l + (warp_m * 64 + mt * 16 + g) * GS + k0 + 2 * t;
                aL[mt][0] = *(const uint32_t*)pl;
                aL[mt][1] = *(const uint32_t*)(pl + 8 * GS);
                aL[mt][2] = *(const uint32_t*)(pl + 8);
                aL[mt][3] = *(const uint32_t*)(pl + 8 * GS + 8);
            }
#pragma unroll
            for (int nt = 0; nt < 4; nt++) {
                const __nv_bfloat16* pb = Bs_h + (warp_n * 32 + nt * 8 + g) * GS + k0 + 2 * t;
                bH[nt][0] = *(const uint32_t*)pb;
                bH[nt][1] = *(const uint32_t*)(pb + 8);
                const __nv_bfloat16* pbl = Bs_l + (warp_n * 32 + nt * 8 + g) * GS + k0 + 2 * t;
                bL[nt][0] = *(const uint32_t*)pbl;
                bL[nt][1] = *(const uint32_t*)(pbl + 8);
            }
#pragma unroll
            for (int mt = 0; mt < 4; mt++)
#pragma unroll
                for (int nt = 0; nt < 4; nt++) {
                    float* dd = d[mt][nt];
                    mma_bf16(dd[0], dd[1], dd[2], dd[3],
                             aH[mt][0], aH[mt][1], aH[mt][2], aH[mt][3],
                             bH[nt][0], bH[nt][1]);
                    mma_bf16(dd[0], dd[1], dd[2], dd[3],
                             aH[mt][0], aH[mt][1], aH[mt][2], aH[mt][3],
                             bL[nt][0], bL[nt][1]);
                    mma_bf16(dd[0], dd[1], dd[2], dd[3],
                             aL[mt][0], aL[mt][1], aL[mt][2], aL[mt][3],
                             bH[nt][0], bH[nt][1]);
                }
        }
        __syncthreads();
    }

#pragma unroll
    for (int mt = 0; mt < 4; mt++) {
        const int row = m0 + warp_m * 64 + mt * 16 + g;
#pragma unroll
        for (int nt = 0; nt < 4; nt++) {
            const int col = n0 + warp_n * 32 + nt * 8 + 2 * t;
            *(float2*)(C + (size_t)row * ldc + col) =
                make_float2(d[mt][nt][0], d[mt][nt][1]);
            *(float2*)(C + (size_t)(row + 8) * ldc + col) =
                make_float2(d[mt][nt][2], d[mt][nt][3]);
        }
    }
}

// ---------------------------------------------------------------------------
// RoPE in-place on Q (heads 0..31) and K (heads 32..39) inside g_qkv.
// ---------------------------------------------------------------------------
__global__ void rope_kernel(const float* __restrict__ cosb,
                            const float* __restrict__ sinb)
{
    int idx = blockIdx.x * blockDim.x + threadIdx.x;
    int p = idx & 63;
    int h = (idx >> 6) % 40;
    int s = idx / (64 * 40);
    float c  = cosb[s * 64 + p];
    float sn = sinb[s * 64 + p];
    float* base = g_qkv + (size_t)s * QKV_W
                + (h < NH ? h * HD : DIM + (h - NH) * HD) + 2 * p;
    float re = base[0], im = base[1];
    base[0] = re * c - im * sn;
    base[1] = re * sn + im * c;
}

// ---------------------------------------------------------------------------
// Tensor-core flash attention.  Block = 128 queries x 1 head, 8 warps,
// each warp owns 16 query rows.  QK^T and PV via mma.sync bf16x3 splits,
// P passed accumulator->A-fragment in registers (FA-2 trick).
// smem (bf16 elems, stride 136 per 128-d row):
//   Qh[128][136] Ql | Kh[64][136] Kl | Vh[64][136] Vl
// ---------------------------------------------------------------------------
#define FS    136                     /* smem row stride (bf16), rows 272 B  */
#define QHO   0
#define QLO   17408
#define KHO   34816
#define KLO   43520
#define VHO   52224
#define VLO   60928
#define FLASH_SMEM2 (69632 * 2)       /* 139264 B */

__global__ void __launch_bounds__(256, 1) flash_mma()
{
    extern __shared__ __nv_bfloat16 sb[];
    const uint32_t sb2 = smem_u32(sb);
    const int qt = blockIdx.x, h = blockIdx.y;
    const int q0 = qt * 128;
    const int kvh = h >> 2;
    const int tid = threadIdx.x;
    const int wid = tid >> 5, lane = tid & 31;
    const int g = lane >> 2, t = lane & 3;
    const int rmin = q0 + wid * 16;               // warp's first query row
    const uint32_t LM = (lane & 15) * FS + ((lane >> 4) << 3);  // ldmatrix lane offset

    // ---- load Q tile (128 x 128) with hi/lo split -----------------------
    const float* qb = g_qkv + (size_t)q0 * QKV_W + h * HD;
#pragma unroll
    for (int p = 0; p < 16; p++) {
        int i = tid + p * 256;            // 0..4095 float4
        int r = i >> 5, c4 = i & 31;
        float4 v = *(const float4*)(qb + (size_t)r * QKV_W + c4 * 4);
        uint2 hh, ll;
        split4(v, hh, ll);
        int o = r * FS + c4 * 4;
        *(uint2*)&sb[QHO + o] = hh;
        *(uint2*)&sb[QLO + o] = ll;
    }

    float m0 = -1e30f, m1 = -1e30f, l0 = 0.f, l1 = 0.f;
    float o[16][4];
#pragma unroll
    for (int i = 0; i < 16; i++)
#pragma unroll
        for (int e = 0; e < 4; e++) o[i][e] = 0.f;

    const float scale = 0.08838834764831845f;     // 1/sqrt(128)
    const int nkt = 2 * (qt + 1);

    for (int kt = 0; kt < nkt; kt++) {
        __syncthreads();                          // smem reuse barrier
        // ---- load K, V tiles (64 x 128 each) with hi/lo split ----------
        const float* kb = g_qkv + (size_t)(kt * 64) * QKV_W + DIM + kvh * HD;
        const float* vb = kb + KVD;
#pragma unroll
        for (int p = 0; p < 8; p++) {
            int i = tid + p * 256;
            int r = i >> 5, c4 = i & 31;
            int o2 = r * FS + c4 * 4;
            float4 kv = *(const float4*)(kb + (size_t)r * QKV_W + c4 * 4);
            uint2 hh, ll;
            split4(kv, hh, ll);
            *(uint2*)&sb[KHO + o2] = hh;
            *(uint2*)&sb[KLO + o2] = ll;
            float4 vv = *(const float4*)(vb + (size_t)r * QKV_W + c4 * 4);
            split4(vv, hh, ll);
            *(uint2*)&sb[VHO + o2] = hh;
            *(uint2*)&sb[VLO + o2] = ll;
        }
        __syncthreads();

        if (kt * 64 > rmin + 15) continue;        // warp fully masked: skip compute

        // ---- S = Q K^T (bf16x3) ----------------------------------------
        float s[8][4];
#pragma unroll
        for (int i = 0; i < 8; i++)
#pragma unroll
            for (int e = 0; e < 4; e++) s[i][e] = 0.f;

#pragma unroll
        for (int ks = 0; ks < 8; ks++) {
            uint32_t qa = sb2 + 2 * (QHO + wid * 16 * FS + LM + ks * 16);
            uint32_t qh0, qh1, qh2, qh3, ql0, ql1, ql2, ql3;
            ldsm4(qh0, qh1, qh2, qh3, qa);
            ldsm4(ql0, ql1, ql2, ql3, qa + 2 * (QLO - QHO));
#pragma unroll
            for (int np = 0; np < 4; np++) {
                uint32_t ka = sb2 + 2 * (KHO + np * 16 * FS + LM + ks * 16);
                uint32_t kh0, kh1, kh2, kh3, kl0, kl1, kl2, kl3;
                ldsm4(kh0, kh1, kh2, kh3, ka);
                ldsm4(kl0, kl1, kl2, kl3, ka + 2 * (KLO - KHO));
                // r0=b0(nt even), r1=b0(nt odd), r2=b1(nt even), r3=b1(nt odd)
                float* se = s[2 * np];
                float* so = s[2 * np + 1];
                mma_bf16(se[0], se[1], se[2], se[3], qh0, qh1, qh2, qh3, kh0, kh2);
                mma_bf16(se[0], se[1], se[2], se[3], qh0, qh1, qh2, qh3, kl0, kl2);
                mma_bf16(se[0], se[1], se[2], se[3], ql0, ql1, ql2, ql3, kh0, kh2);
                mma_bf16(so[0], so[1], so[2], so[3], qh0, qh1, qh2, qh3, kh1, kh3);
                mma_bf16(so[0], so[1], so[2], so[3], qh0, qh1, qh2, qh3, kl1, kl3);
                mma_bf16(so[0], so[1], so[2], so[3], ql0, ql1, ql2, ql3, kh1, kh3);
            }
        }

        // ---- scale + causal mask ---------------------------------------
        const bool dm = (kt * 64 + 63) > rmin;
#pragma unroll
        for (int nt = 0; nt < 8; nt++) {
            int colb = kt * 64 + nt * 8 + 2 * t;
#pragma unroll
            for (int e = 0; e < 4; e++) {
                float v = s[nt][e] * scale;
                if (dm && (colb + (e & 1)) > (rmin + g + (e >> 1) * 8)) v = -1e30f;
                s[nt][e] = v;
            }
        }

        // ---- online softmax (rows g and g+8 per lane) ------------------
        float rm0 = -1e30f, rm1 = -1e30f;
#pragma unroll
        for (int nt = 0; nt < 8; nt++) {
            rm0 = fmaxf(rm0, fmaxf(s[nt][0], s[nt][1]));
            rm1 = fmaxf(rm1, fmaxf(s[nt][2], s[nt][3]));
        }
        rm0 = fmaxf(rm0, __shfl_xor_sync(0xffffffffu, rm0, 1));
        rm0 = fmaxf(rm0, __shfl_xor_sync(0xffffffffu, rm0, 2));
        rm1 = fmaxf(rm1, __shfl_xor_sync(0xffffffffu, rm1, 1));
        rm1 = fmaxf(rm1, __shfl_xor_sync(0xffffffffu, rm1, 2));
        float mn0 = fmaxf(m0, rm0), mn1 = fmaxf(m1, rm1);
        float a0 = __expf(m0 - mn0), a1 = __expf(m1 - mn1);
        m0 = mn0; m1 = mn1;
        float ls0 = 0.f, ls1 = 0.f;
#pragma unroll
        for (int nt = 0; nt < 8; nt++) {
            s[nt][0] = __expf(s[nt][0] - mn0);
            s[nt][1] = __expf(s[nt][1] - mn0);
            s[nt][2] = __expf(s[nt][2] - mn1);
            s[nt][3] = __expf(s[nt][3] - mn1);
            ls0 += s[nt][0] + s[nt][1];
            ls1 += s[nt][2] + s[nt][3];
        }
        ls0 += __shfl_xor_sync(0xffffffffu, ls0, 1);
        ls0 += __shfl_xor_sync(0xffffffffu, ls0, 2);
        ls1 += __shfl_xor_sync(0xffffffffu, ls1, 1);
        ls1 += __shfl_xor_sync(0xffffffffu, ls1, 2);
        l0 = l0 * a0 + ls0;
        l1 = l1 * a1 + ls1;
#pragma unroll
        for (int nt = 0; nt < 16; nt++) {
            o[nt][0] *= a0; o[nt][1] *= a0;
            o[nt][2] *= a1; o[nt][3] *= a1;
        }

        // ---- P -> bf16 hi/lo A-fragments (register pass) ---------------
        uint32_t pah[4][4], pal[4][4];
#pragma unroll
        for (int k2 = 0; k2 < 4; k2++) {
            split2(s[2 * k2][0],     s[2 * k2][1],     pah[k2][0], pal[k2][0]);
            split2(s[2 * k2][2],     s[2 * k2][3],     pah[k2][1], pal[k2][1]);
            split2(s[2 * k2 + 1][0], s[2 * k2 + 1][1], pah[k2][2], pal[k2][2]);
            split2(s[2 * k2 + 1][2], s[2 * k2 + 1][3], pah[k2][3], pal[k2][3]);
        }

        // ---- O += P V (bf16x3, V frags via ldmatrix.trans) -------------
#pragma unroll
        for (int k2 = 0; k2 < 4; k2++) {
#pragma unroll
            for (int np = 0; np < 8; np++) {
                uint32_t va = sb2 + 2 * (VHO + k2 * 16 * FS + LM + np * 16);
                uint32_t vh0, vh1, vh2, vh3, vl0, vl1, vl2, vl3;
                ldsm4t(vh0, vh1, vh2, vh3, va);
                ldsm4t(vl0, vl1, vl2, vl3, va + 2 * (VLO - VHO));
                // (r0,r1) = frag for d-tile 2np, (r2,r3) = d-tile 2np+1
                float* oe = o[2 * np];
                float* oo = o[2 * np + 1];
                mma_bf16(oe[0], oe[1], oe[2], oe[3],
                         pah[k2][0], pah[k2][1], pah[k2][2], pah[k2][3], vh0, vh1);
                mma_bf16(oe[0], oe[1], oe[2], oe[3],
                         pal[k2][0], pal[k2][1], pal[k2][2], pal[k2][3], vh0, vh1);
                mma_bf16(oe[0], oe[1], oe[2], oe[3],
                         pah[k2][0], pah[k2][1], pah[k2][2], pah[k2][3], vl0, vl1);
                mma_bf16(oo[0], oo[1], oo[2], oo[3],
                         pah[k2][0], pah[k2][1], pah[k2][2], pah[k2][3], vh2, vh3);
                mma_bf16(oo[0], oo[1], oo[2], oo[3],
                         pal[k2][0], pal[k2][1], pal[k2][2], pal[k2][3], vh2, vh3);
                mma_bf16(oo[0], oo[1], oo[2], oo[3],
                         pah[k2][0], pah[k2][1], pah[k2][2], pah[k2][3], vl2, vl3);
            }
        }
    }

    // ---- epilogue: O /= l, store to g_attn ------------------------------
    float i0 = 1.f / l0, i1 = 1.f / l1;
    float* op0 = g_attn + (size_t)(rmin + g) * DIM + h * HD;
    float* op1 = g_attn + (size_t)(rmin + g + 8) * DIM + h * HD;
#pragma unroll
    for (int nt = 0; nt < 16; nt++) {
        int col = nt * 8 + 2 * t;
        *(float2*)(op0 + col) = make_float2(o[nt][0] * i0, o[nt][1] * i0);
        *(float2*)(op1 + col) = make_float2(o[nt][2] * i1, o[nt][3] * i1);
    }
}

// ---------------------------------------------------------------------------
extern "C" void kernel_launch(void* const* d_in, const int* in_sizes, int n_in,
                              void* d_out, int out_size)
{
    const float* x  = (const float*)d_in[0];
    const float* wq = (const float*)d_in[1];
    const float* wk = (const float*)d_in[2];
    const float* wv = (const float*)d_in[3];
    const float* wo = (const float*)d_in[4];
    const float* fc = (const float*)d_in[7];
    const float* fs = (const float*)d_in[8];
    float* out = (float*)d_out;
    (void)in_sizes; (void)n_in; (void)out_size;

    static float *qkv = nullptr, *attn = nullptr;
    static __nv_bfloat16 *xh, *xl, *wqh, *wql, *wkh, *wkl, *wvh, *wvl, *woh, *wol, *ah, *al;
    if (!qkv) {   // first call is the uncaptured correctness run
        cudaGetSymbolAddress((void**)&qkv, g_qkv);
        cudaGetSymbolAddress((void**)&attn, g_attn);
        cudaGetSymbolAddress((void**)&xh, g_xh);   cudaGetSymbolAddress((void**)&xl, g_xl);
        cudaGetSymbolAddress((void**)&wqh, g_wqh); cudaGetSymbolAddress((void**)&wql, g_wql);
        cudaGetSymbolAddress((void**)&wkh, g_wkh); cudaGetSymbolAddress((void**)&wkl, g_wkl);
        cudaGetSymbolAddress((void**)&wvh, g_wvh); cudaGetSymbolAddress((void**)&wvl, g_wvl);
        cudaGetSymbolAddress((void**)&woh, g_woh); cudaGetSymbolAddress((void**)&wol, g_wol);
        cudaGetSymbolAddress((void**)&ah, g_ah);   cudaGetSymbolAddress((void**)&al, g_al);
        cudaFuncSetAttribute(gemm_mma,
                             cudaFuncAttributeMaxDynamicSharedMemorySize, GEMM_SMEM);
        cudaFuncSetAttribute(flash_mma,
                             cudaFuncAttributeMaxDynamicSharedMemorySize, FLASH_SMEM2);
    }

    // fp32 -> bf16 hi/lo splits
    split_kernel<<<(SEQ * DIM / 4 + 255) / 256, 256>>>(x, xh, xl, SEQ * DIM / 4);
    split_kernel<<<(DIM * DIM / 4 + 255) / 256, 256>>>(wq, wqh, wql, DIM * DIM / 4);
    split_kernel<<<(KVD * DIM / 4 + 255) / 256, 256>>>(wk, wkh, wkl, KVD * DIM / 4);
    split_kernel<<<(KVD * DIM / 4 + 255) / 256, 256>>>(wv, wvh, wvl, KVD * DIM / 4);
    split_kernel<<<(DIM * DIM / 4 + 255) / 256, 256>>>(wo, woh, wol, DIM * DIM / 4);

    // QKV projections (HMMA, bf16x3) into fused [S, 6144] scratch
    gemm_mma<<<dim3(DIM / 128, SEQ / 128), 256, GEMM_SMEM>>>(xh, xl, wqh, wql, qkv, QKV_W, DIM);
    gemm_mma<<<dim3(KVD / 128, SEQ / 128), 256, GEMM_SMEM>>>(xh, xl, wkh, wkl, qkv + DIM, QKV_W, DIM);
    gemm_mma<<<dim3(KVD / 128, SEQ / 128), 256, GEMM_SMEM>>>(xh, xl, wvh, wvl, qkv + DIM + KVD, QKV_W, DIM);

    // RoPE on Q + K in place
    rope_kernel<<<SEQ * 40 * 64 / 256, 256>>>(fc, fs);

    // Causal GQA flash attention (tensor cores) -> g_attn [S, 4096]
    flash_mma<<<dim3(SEQ / 128, NH), 256, FLASH_SMEM2>>>();

    // Output projection (HMMA)
    split_kernel<<<(SEQ * DIM / 4 + 255) / 256, 256>>>(attn, ah, al, SEQ * DIM / 4);
    gemm_mma<<<dim3(DIM / 128, SEQ / 128), 256, GEMM_SMEM>>>(ah, al, woh, wol, out, DIM, DIM);
}

// round 7
// speedup vs baseline: 3.1341x; 1.0842x over previous
#include <cuda_runtime.h>
#include <cuda_bf16.h>
#include <math.h>
#include <cstdint>

#define SEQ   2048
#define DIM   4096
#define NH    32
#define NKV   8
#define HD    128
#define KVD   (NKV * HD)             /* 1024 */
#define QKV_W (DIM + 2 * KVD)        /* 6144: [q 4096 | k 1024 | v 1024] per row */

// ---------------------------------------------------------------------------
// Scratch (__device__ globals — the sanctioned allocation mechanism)
// ---------------------------------------------------------------------------
__device__ float g_qkv[SEQ * QKV_W];
__device__ float g_attn[SEQ * DIM];
__device__ __nv_bfloat16 g_xh[SEQ * DIM],   g_xl[SEQ * DIM];
__device__ __nv_bfloat16 g_wAh[QKV_W * DIM], g_wAl[QKV_W * DIM];  // wq|wk|wv fused
__device__ __nv_bfloat16 g_woh[DIM * DIM],  g_wol[DIM * DIM];
__device__ __nv_bfloat16 g_ah[SEQ * DIM],   g_al[SEQ * DIM];

// ---------------------------------------------------------------------------
// helpers
// ---------------------------------------------------------------------------
__device__ __forceinline__ uint32_t smem_u32(const void* p) {
    uint32_t a;
    asm("{ .reg .u64 t; cvta.to.shared.u64 t, %1; cvt.u32.u64 %0, t; }"
        : "=r"(a) : "l"(p));
    return a;
}
__device__ __forceinline__ void cp_async16(uint32_t dst, const void* src) {
    asm volatile("cp.async.cg.shared.global [%0], [%1], 16;"
                 :: "r"(dst), "l"(src));
}
__device__ __forceinline__ void mma_bf16(float& d0, float& d1, float& d2, float& d3,
                                         uint32_t a0, uint32_t a1, uint32_t a2, uint32_t a3,
                                         uint32_t b0, uint32_t b1)
{
    asm volatile(
        "mma.sync.aligned.m16n8k16.row.col.f32.bf16.bf16.f32 "
        "{%0,%1,%2,%3}, {%4,%5,%6,%7}, {%8,%9}, {%0,%1,%2,%3};"
        : "+f"(d0), "+f"(d1), "+f"(d2), "+f"(d3)
        : "r"(a0), "r"(a1), "r"(a2), "r"(a3), "r"(b0), "r"(b1));
}
__device__ __forceinline__ void ldsm4(uint32_t& r0, uint32_t& r1, uint32_t& r2,
                                      uint32_t& r3, uint32_t a)
{
    asm volatile("ldmatrix.sync.aligned.m8n8.x4.shared.b16 {%0,%1,%2,%3}, [%4];"
                 : "=r"(r0), "=r"(r1), "=r"(r2), "=r"(r3) : "r"(a));
}
__device__ __forceinline__ void ldsm4t(uint32_t& r0, uint32_t& r1, uint32_t& r2,
                                       uint32_t& r3, uint32_t a)
{
    asm volatile("ldmatrix.sync.aligned.m8n8.x4.trans.shared.b16 {%0,%1,%2,%3}, [%4];"
                 : "=r"(r0), "=r"(r1), "=r"(r2), "=r"(r3) : "r"(a));
}
__device__ __forceinline__ void split4(float4 v, uint2& h, uint2& l) {
    __nv_bfloat16 h0 = __float2bfloat16(v.x), h1 = __float2bfloat16(v.y);
    __nv_bfloat16 h2 = __float2bfloat16(v.z), h3 = __float2bfloat16(v.w);
    __nv_bfloat162 ha(h0, h1), hb(h2, h3);
    __nv_bfloat162 la(__float2bfloat16(v.x - __bfloat162float(h0)),
                      __float2bfloat16(v.y - __bfloat162float(h1)));
    __nv_bfloat162 lb(__float2bfloat16(v.z - __bfloat162float(h2)),
                      __float2bfloat16(v.w - __bfloat162float(h3)));
    h = make_uint2(*(uint32_t*)&ha, *(uint32_t*)&hb);
    l = make_uint2(*(uint32_t*)&la, *(uint32_t*)&lb);
}
__device__ __forceinline__ void split2(float x, float y, uint32_t& h, uint32_t& l) {
    __nv_bfloat16 hx = __float2bfloat16(x), hy = __float2bfloat16(y);
    __nv_bfloat162 hv(hx, hy);
    __nv_bfloat162 lv(__float2bfloat16(x - __bfloat162float(hx)),
                      __float2bfloat16(y - __bfloat162float(hy)));
    h = *(uint32_t*)&hv;
    l = *(uint32_t*)&lv;
}

// ---------------------------------------------------------------------------
// fp32 -> bf16 hi/lo split (vectorized x4)
// ---------------------------------------------------------------------------
__global__ void split_kernel(const float* __restrict__ src,
                             __nv_bfloat16* __restrict__ hi,
                             __nv_bfloat16* __restrict__ lo, int n4)
{
    int i = blockIdx.x * blockDim.x + threadIdx.x;
    if (i >= n4) return;
    float4 v = ((const float4*)src)[i];
    uint2 h, l;
    split4(v, h, l);
    ((uint2*)hi)[i] = h;
    ((uint2*)lo)[i] = l;
}

// ---------------------------------------------------------------------------
// HMMA GEMM v2: C[M,N] = A[M,K] * B[N,K]^T, bf16x3 split, fp32 accum.
// 128x256 block tile, warp tile 64x64 (8 warps 2x4), BK=32.
// smem rows are 64 B (32 bf16) with XOR chunk swizzle c' = c ^ ((r>>1)&3):
// conflict-free for both cp.async 16B writes and ldmatrix reads.
// 4-stage cp.async pipeline.
// ---------------------------------------------------------------------------
#define AH3   0
#define AL3   (128 * 32)                 /* 4096  halfs */
#define BH3   (2 * 128 * 32)             /* 8192  halfs */
#define BL3   (BH3 + 256 * 32)           /* 16384 halfs */
#define STG3  (BH3 + 2 * 256 * 32)       /* 24576 halfs = 49152 B */
#define GEMM_SMEM (4 * STG3 * 2)         /* 196608 B */

__global__ void __launch_bounds__(256, 1) gemm_mma2(
    const __nv_bfloat16* __restrict__ Ah, const __nv_bfloat16* __restrict__ Al,
    const __nv_bfloat16* __restrict__ Bh, const __nv_bfloat16* __restrict__ Bl,
    float* __restrict__ C, int ldc, int K)
{
    extern __shared__ __nv_bfloat16 sm3[];
    const uint32_t sbase = smem_u32(sm3);
    const int tid = threadIdx.x;
    const int wid = tid >> 5, lane = tid & 31;
    const int warp_m = wid & 1, warp_n = wid >> 1;      // 2 x 4 warp grid
    const int g = lane >> 2, t = lane & 3;
    const int m0 = blockIdx.y * 128, n0 = blockIdx.x * 256;

    // ldmatrix lane offsets (halfs) for ks = 0,1 within a 16-row tile
    const int rl = lane & 15;
    const int sw = (rl >> 1) & 3;
    const int ch = lane >> 4;
    const uint32_t LM0 = rl * 32 + (((ch + 0) ^ sw) << 3);
    const uint32_t LM1 = rl * 32 + (((ch + 2) ^ sw) << 3);

    const __nv_bfloat16* gAh = Ah + (size_t)m0 * K;
    const __nv_bfloat16* gAl = Al + (size_t)m0 * K;
    const __nv_bfloat16* gBh = Bh + (size_t)n0 * K;
    const __nv_bfloat16* gBl = Bl + (size_t)n0 * K;

    float d[4][8][4];
#pragma unroll
    for (int i = 0; i < 4; i++)
#pragma unroll
        for (int j = 0; j < 8; j++)
#pragma unroll
            for (int e = 0; e < 4; e++) d[i][j][e] = 0.f;

    const int nk = K / 32;

    // stage loader: A-h/A-l 128 rows, B-h/B-l 256 rows, 4 x 16B chunks per row
    auto issue = [&](int s, int buf) {
        const int koff = s * 32;
        const uint32_t stg = sbase + (uint32_t)buf * (STG3 * 2);
#pragma unroll
        for (int j = 0; j < 12; j++) {
            int idx = tid + j * 256;                 // 0..3071
            const __nv_bfloat16* src;
            uint32_t off;
            int r, rows_off;
            if (idx < 512)       { r = idx >> 2;            src = gAh; off = AH3; }
            else if (idx < 1024) { r = (idx - 512) >> 2;    src = gAl; off = AL3; }
            else if (idx < 2048) { r = (idx - 1024) >> 2;   src = gBh; off = BH3; }
            else                 { r = (idx - 2048) >> 2;   src = gBl; off = BL3; }
            int c = idx & 3;
            int cs = c ^ ((r >> 1) & 3);
            cp_async16(stg + 2 * (off + r * 32 + cs * 8),
                       src + (size_t)r * K + koff + c * 8);
        }
        asm volatile("cp.async.commit_group;" ::: "memory");
    };

    issue(0, 0);
    if (nk > 1) issue(1, 1);
    if (nk > 2) issue(2, 2);

    for (int s = 0; s < nk; s++) {
        const int buf = s & 3;
        if (s + 2 < nk)      asm volatile("cp.async.wait_group 2;" ::: "memory");
        else if (s + 1 < nk) asm volatile("cp.async.wait_group 1;" ::: "memory");
        else                 asm volatile("cp.async.wait_group 0;" ::: "memory");
        __syncthreads();
        if (s + 3 < nk) issue(s + 3, (s + 3) & 3);

        const uint32_t stg = sbase + (uint32_t)buf * (STG3 * 2);

#pragma unroll
        for (int ks = 0; ks < 2; ks++) {
            const uint32_t LM = ks ? LM1 : LM0;
            uint32_t aH[4][4], aL[4][4];
#pragma unroll
            for (int mt = 0; mt < 4; mt++) {
                uint32_t abase = stg + 2 * ((warp_m * 64 + mt * 16) * 32 + LM);
                ldsm4(aH[mt][0], aH[mt][1], aH[mt][2], aH[mt][3], abase + 2 * AH3);
                ldsm4(aL[mt][0], aL[mt][1], aL[mt][2], aL[mt][3], abase + 2 * AL3);
            }
#pragma unroll
            for (int ng = 0; ng < 4; ng++) {
                uint32_t bbase = stg + 2 * ((warp_n * 64 + ng * 16) * 32 + LM);
                uint32_t bh0, bh1, bh2, bh3, bl0, bl1, bl2, bl3;
                ldsm4(bh0, bh1, bh2, bh3, bbase + 2 * BH3);
                ldsm4(bl0, bl1, bl2, bl3, bbase + 2 * BL3);
#pragma unroll
                for (int mt = 0; mt < 4; mt++) {
                    float* de = d[mt][2 * ng];
                    float* dо = d[mt][2 * ng + 1];
                    mma_bf16(de[0], de[1], de[2], de[3],
                             aH[mt][0], aH[mt][1], aH[mt][2], aH[mt][3], bh0, bh2);
                    mma_bf16(de[0], de[1], de[2], de[3],
                             aH[mt][0], aH[mt][1], aH[mt][2], aH[mt][3], bl0, bl2);
                    mma_bf16(de[0], de[1], de[2], de[3],
                             aL[mt][0], aL[mt][1], aL[mt][2], aL[mt][3], bh0, bh2);
                    mma_bf16(dо[0], dо[1], dо[2], dо[3],
                             aH[mt][0], aH[mt][1], aH[mt][2], aH[mt][3], bh1, bh3);
                    mma_bf16(dо[0], dо[1], dо[2], dо[3],
                             aH[mt][0], aH[mt][1], aH[mt][2], aH[mt][3], bl1, bl3);
                    mma_bf16(dо[0], dо[1], dо[2], dо[3],
                             aL[mt][0], aL[mt][1], aL[mt][2], aL[mt][3], bh1, bh3);
                }
            }
        }
        __syncthreads();
    }

    // epilogue
#pragma unroll
    for (int mt = 0; mt < 4; mt++) {
        const int row = m0 + warp_m * 64 + mt * 16 + g;
#pragma unroll
        for (int nt = 0; nt < 8; nt++) {
            const int col = n0 + warp_n * 64 + nt * 8 + 2 * t;
            *(float2*)(C + (size_t)row * ldc + col) =
                make_float2(d[mt][nt][0], d[mt][nt][1]);
            *(float2*)(C + (size_t)(row + 8) * ldc + col) =
                make_float2(d[mt][nt][2], d[mt][nt][3]);
        }
    }
}

// ---------------------------------------------------------------------------
// RoPE in-place on Q (heads 0..31) and K (heads 32..39) inside g_qkv.
// ---------------------------------------------------------------------------
__global__ void rope_kernel(const float* __restrict__ cosb,
                            const float* __restrict__ sinb)
{
    int idx = blockIdx.x * blockDim.x + threadIdx.x;
    int p = idx & 63;
    int h = (idx >> 6) % 40;
    int s = idx / (64 * 40);
    float c  = cosb[s * 64 + p];
    float sn = sinb[s * 64 + p];
    float* base = g_qkv + (size_t)s * QKV_W
                + (h < NH ? h * HD : DIM + (h - NH) * HD) + 2 * p;
    float re = base[0], im = base[1];
    base[0] = re * c - im * sn;
    base[1] = re * sn + im * c;
}

// ---------------------------------------------------------------------------
// Tensor-core flash attention (unchanged from R6).  Block = 128 q x 1 head,
// 8 warps x 16 rows.  QK^T and PV via mma.sync bf16x3, P in registers.
// ---------------------------------------------------------------------------
#define FS    136
#define QHO   0
#define QLO   17408
#define KHO   34816
#define KLO   43520
#define VHO   52224
#define VLO   60928
#define FLASH_SMEM2 (69632 * 2)

__global__ void __launch_bounds__(256, 1) flash_mma()
{
    extern __shared__ __nv_bfloat16 sb[];
    const uint32_t sb2 = smem_u32(sb);
    const int qt = blockIdx.x, h = blockIdx.y;
    const int q0 = qt * 128;
    const int kvh = h >> 2;
    const int tid = threadIdx.x;
    const int wid = tid >> 5, lane = tid & 31;
    const int g = lane >> 2, t = lane & 3;
    const int rmin = q0 + wid * 16;
    const uint32_t LM = (lane & 15) * FS + ((lane >> 4) << 3);

    const float* qb = g_qkv + (size_t)q0 * QKV_W + h * HD;
#pragma unroll
    for (int p = 0; p < 16; p++) {
        int i = tid + p * 256;
        int r = i >> 5, c4 = i & 31;
        float4 v = *(const float4*)(qb + (size_t)r * QKV_W + c4 * 4);
        uint2 hh, ll;
        split4(v, hh, ll);
        int o = r * FS + c4 * 4;
        *(uint2*)&sb[QHO + o] = hh;
        *(uint2*)&sb[QLO + o] = ll;
    }

    float m0 = -1e30f, m1 = -1e30f, l0 = 0.f, l1 = 0.f;
    float o[16][4];
#pragma unroll
    for (int i = 0; i < 16; i++)
#pragma unroll
        for (int e = 0; e < 4; e++) o[i][e] = 0.f;

    const float scale = 0.08838834764831845f;
    const int nkt = 2 * (qt + 1);

    for (int kt = 0; kt < nkt; kt++) {
        __syncthreads();
        const float* kb = g_qkv + (size_t)(kt * 64) * QKV_W + DIM + kvh * HD;
        const float* vb = kb + KVD;
#pragma unroll
        for (int p = 0; p < 8; p++) {
            int i = tid + p * 256;
            int r = i >> 5, c4 = i & 31;
            int o2 = r * FS + c4 * 4;
            float4 kv = *(const float4*)(kb + (size_t)r * QKV_W + c4 * 4);
            uint2 hh, ll;
            split4(kv, hh, ll);
            *(uint2*)&sb[KHO + o2] = hh;
            *(uint2*)&sb[KLO + o2] = ll;
            float4 vv = *(const float4*)(vb + (size_t)r * QKV_W + c4 * 4);
            split4(vv, hh, ll);
            *(uint2*)&sb[VHO + o2] = hh;
            *(uint2*)&sb[VLO + o2] = ll;
        }
        __syncthreads();

        if (kt * 64 > rmin + 15) continue;

        float s[8][4];
#pragma unroll
        for (int i = 0; i < 8; i++)
#pragma unroll
            for (int e = 0; e < 4; e++) s[i][e] = 0.f;

#pragma unroll
        for (int ks = 0; ks < 8; ks++) {
            uint32_t qa = sb2 + 2 * (QHO + wid * 16 * FS + LM + ks * 16);
            uint32_t qh0, qh1, qh2, qh3, ql0, ql1, ql2, ql3;
            ldsm4(qh0, qh1, qh2, qh3, qa);
            ldsm4(ql0, ql1, ql2, ql3, qa + 2 * (QLO - QHO));
#pragma unroll
            for (int np = 0; np < 4; np++) {
                uint32_t ka = sb2 + 2 * (KHO + np * 16 * FS + LM + ks * 16);
                uint32_t kh0, kh1, kh2, kh3, kl0, kl1, kl2, kl3;
                ldsm4(kh0, kh1, kh2, kh3, ka);
                ldsm4(kl0, kl1, kl2, kl3, ka + 2 * (KLO - KHO));
                float* se = s[2 * np];
                float* so = s[2 * np + 1];
                mma_bf16(se[0], se[1], se[2], se[3], qh0, qh1, qh2, qh3, kh0, kh2);
                mma_bf16(se[0], se[1], se[2], se[3], qh0, qh1, qh2, qh3, kl0, kl2);
                mma_bf16(se[0], se[1], se[2], se[3], ql0, ql1, ql2, ql3, kh0, kh2);
                mma_bf16(so[0], so[1], so[2], so[3], qh0, qh1, qh2, qh3, kh1, kh3);
                mma_bf16(so[0], so[1], so[2], so[3], qh0, qh1, qh2, qh3, kl1, kl3);
                mma_bf16(so[0], so[1], so[2], so[3], ql0, ql1, ql2, ql3, kh1, kh3);
            }
        }

        const bool dm = (kt * 64 + 63) > rmin;
#pragma unroll
        for (int nt = 0; nt < 8; nt++) {
            int colb = kt * 64 + nt * 8 + 2 * t;
#pragma unroll
            for (int e = 0; e < 4; e++) {
                float v = s[nt][e] * scale;
                if (dm && (colb + (e & 1)) > (rmin + g + (e >> 1) * 8)) v = -1e30f;
                s[nt][e] = v;
            }
        }

        float rm0 = -1e30f, rm1 = -1e30f;
#pragma unroll
        for (int nt = 0; nt < 8; nt++) {
            rm0 = fmaxf(rm0, fmaxf(s[nt][0], s[nt][1]));
            rm1 = fmaxf(rm1, fmaxf(s[nt][2], s[nt][3]));
        }
        rm0 = fmaxf(rm0, __shfl_xor_sync(0xffffffffu, rm0, 1));
        rm0 = fmaxf(rm0, __shfl_xor_sync(0xffffffffu, rm0, 2));
        rm1 = fmaxf(rm1, __shfl_xor_sync(0xffffffffu, rm1, 1));
        rm1 = fmaxf(rm1, __shfl_xor_sync(0xffffffffu, rm1, 2));
        float mn0 = fmaxf(m0, rm0), mn1 = fmaxf(m1, rm1);
        float a0 = __expf(m0 - mn0), a1 = __expf(m1 - mn1);
        m0 = mn0; m1 = mn1;
        float ls0 = 0.f, ls1 = 0.f;
#pragma unroll
        for (int nt = 0; nt < 8; nt++) {
            s[nt][0] = __expf(s[nt][0] - mn0);
            s[nt][1] = __expf(s[nt][1] - mn0);
            s[nt][2] = __expf(s[nt][2] - mn1);
            s[nt][3] = __expf(s[nt][3] - mn1);
            ls0 += s[nt][0] + s[nt][1];
            ls1 += s[nt][2] + s[nt][3];
        }
        ls0 += __shfl_xor_sync(0xffffffffu, ls0, 1);
        ls0 += __shfl_xor_sync(0xffffffffu, ls0, 2);
        ls1 += __shfl_xor_sync(0xffffffffu, ls1, 1);
        ls1 += __shfl_xor_sync(0xffffffffu, ls1, 2);
        l0 = l0 * a0 + ls0;
        l1 = l1 * a1 + ls1;
#pragma unroll
        for (int nt = 0; nt < 16; nt++) {
            o[nt][0] *= a0; o[nt][1] *= a0;
            o[nt][2] *= a1; o[nt][3] *= a1;
        }

        uint32_t pah[4][4], pal[4][4];
#pragma unroll
        for (int k2 = 0; k2 < 4; k2++) {
            split2(s[2 * k2][0],     s[2 * k2][1],     pah[k2][0], pal[k2][0]);
            split2(s[2 * k2][2],     s[2 * k2][3],     pah[k2][1], pal[k2][1]);
            split2(s[2 * k2 + 1][0], s[2 * k2 + 1][1], pah[k2][2], pal[k2][2]);
            split2(s[2 * k2 + 1][2], s[2 * k2 + 1][3], pah[k2][3], pal[k2][3]);
        }

#pragma unroll
        for (int k2 = 0; k2 < 4; k2++) {
#pragma unroll
            for (int np = 0; np < 8; np++) {
                uint32_t va = sb2 + 2 * (VHO + k2 * 16 * FS + LM + np * 16);
                uint32_t vh0, vh1, vh2, vh3, vl0, vl1, vl2, vl3;
                ldsm4t(vh0, vh1, vh2, vh3, va);
                ldsm4t(vl0, vl1, vl2, vl3, va + 2 * (VLO - VHO));
                float* oe = o[2 * np];
                float* oo = o[2 * np + 1];
                mma_bf16(oe[0], oe[1], oe[2], oe[3],
                         pah[k2][0], pah[k2][1], pah[k2][2], pah[k2][3], vh0, vh1);
                mma_bf16(oe[0], oe[1], oe[2], oe[3],
                         pal[k2][0], pal[k2][1], pal[k2][2], pal[k2][3], vh0, vh1);
                mma_bf16(oe[0], oe[1], oe[2], oe[3],
                         pah[k2][0], pah[k2][1], pah[k2][2], pah[k2][3], vl0, vl1);
                mma_bf16(oo[0], oo[1], oo[2], oo[3],
                         pah[k2][0], pah[k2][1], pah[k2][2], pah[k2][3], vh2, vh3);
                mma_bf16(oo[0], oo[1], oo[2], oo[3],
                         pal[k2][0], pal[k2][1], pal[k2][2], pal[k2][3], vh2, vh3);
                mma_bf16(oo[0], oo[1], oo[2], oo[3],
                         pah[k2][0], pah[k2][1], pah[k2][2], pah[k2][3], vl2, vl3);
            }
        }
    }

    float i0 = 1.f / l0, i1 = 1.f / l1;
    float* op0 = g_attn + (size_t)(rmin + g) * DIM + h * HD;
    float* op1 = g_attn + (size_t)(rmin + g + 8) * DIM + h * HD;
#pragma unroll
    for (int nt = 0; nt < 16; nt++) {
        int col = nt * 8 + 2 * t;
        *(float2*)(op0 + col) = make_float2(o[nt][0] * i0, o[nt][1] * i0);
        *(float2*)(op1 + col) = make_float2(o[nt][2] * i1, o[nt][3] * i1);
    }
}

// ---------------------------------------------------------------------------
extern "C" void kernel_launch(void* const* d_in, const int* in_sizes, int n_in,
                              void* d_out, int out_size)
{
    const float* x  = (const float*)d_in[0];
    const float* wq = (const float*)d_in[1];
    const float* wk = (const float*)d_in[2];
    const float* wv = (const float*)d_in[3];
    const float* wo = (const float*)d_in[4];
    const float* fc = (const float*)d_in[7];
    const float* fs = (const float*)d_in[8];
    float* out = (float*)d_out;
    (void)in_sizes; (void)n_in; (void)out_size;

    static float *qkv = nullptr, *attn = nullptr;
    static __nv_bfloat16 *xh, *xl, *wAh, *wAl, *woh, *wol, *ah, *al;
    if (!qkv) {   // first call is the uncaptured correctness run
        cudaGetSymbolAddress((void**)&qkv, g_qkv);
        cudaGetSymbolAddress((void**)&attn, g_attn);
        cudaGetSymbolAddress((void**)&xh, g_xh);   cudaGetSymbolAddress((void**)&xl, g_xl);
        cudaGetSymbolAddress((void**)&wAh, g_wAh); cudaGetSymbolAddress((void**)&wAl, g_wAl);
        cudaGetSymbolAddress((void**)&woh, g_woh); cudaGetSymbolAddress((void**)&wol, g_wol);
        cudaGetSymbolAddress((void**)&ah, g_ah);   cudaGetSymbolAddress((void**)&al, g_al);
        cudaFuncSetAttribute(gemm_mma2,
                             cudaFuncAttributeMaxDynamicSharedMemorySize, GEMM_SMEM);
        cudaFuncSetAttribute(flash_mma,
                             cudaFuncAttributeMaxDynamicSharedMemorySize, FLASH_SMEM2);
    }

    // fp32 -> bf16 hi/lo splits (wq|wk|wv fused into one [6144 x 4096] buffer)
    split_kernel<<<(SEQ * DIM / 4 + 255) / 256, 256>>>(x, xh, xl, SEQ * DIM / 4);
    split_kernel<<<(DIM * DIM / 4 + 255) / 256, 256>>>(wq, wAh, wAl, DIM * DIM / 4);
    split_kernel<<<(KVD * DIM / 4 + 255) / 256, 256>>>(
        wk, wAh + (size_t)DIM * DIM, wAl + (size_t)DIM * DIM, KVD * DIM / 4);
    split_kernel<<<(KVD * DIM / 4 + 255) / 256, 256>>>(
        wv, wAh + (size_t)(DIM + KVD) * DIM, wAl + (size_t)(DIM + KVD) * DIM, KVD * DIM / 4);
    split_kernel<<<(DIM * DIM / 4 + 255) / 256, 256>>>(wo, woh, wol, DIM * DIM / 4);

    // Fused QKV projection (one GEMM, N = 6144) -> g_qkv [S, 6144]
    gemm_mma2<<<dim3(QKV_W / 256, SEQ / 128), 256, GEMM_SMEM>>>(
        xh, xl, wAh, wAl, qkv, QKV_W, DIM);

    // RoPE on Q + K in place
    rope_kernel<<<SEQ * 40 * 64 / 256, 256>>>(fc, fs);

    // Causal GQA flash attention (tensor cores) -> g_attn [S, 4096]
    flash_mma<<<dim3(SEQ / 128, NH), 256, FLASH_SMEM2>>>();

    // Output projection
    split_kernel<<<(SEQ * DIM / 4 + 255) / 256, 256>>>(attn, ah, al, SEQ * DIM / 4);
    gemm_mma2<<<dim3(DIM / 256, SEQ / 128), 256, GEMM_SMEM>>>(
        ah, al, woh, wol, out, DIM, DIM);
}